// round 5
// baseline (speedup 1.0000x reference)
#include <cuda_runtime.h>
#include <cuda_fp16.h>
#include <cstdint>
#include <cstddef>

// ---------------------------------------------------------------------------
// Problem constants
// ---------------------------------------------------------------------------
constexpr int NN  = 8192;   // nodes
constexpr int FIN = 256;    // input features
constexpr int HC  = 128;    // fused hidden columns (h1 | h2)

// GEMM tiling (single-pass fp16 mma.sync)
constexpr int BM = 128, BN = 128, BKk = 32;
constexpr int KHALF = NN / 2;           // 4096
constexpr int NT = KHALF / BKk;         // 128 iters
constexpr int ROWB = 80;                // padded smem row stride (bytes)
constexpr int OA = 0;
constexpr int OB = BM * ROWB;           // 10240
constexpr int STAGE = OB + BN * ROWB;   // 20480 bytes / stage
constexpr int NSTG = 3;
constexpr int DYN_SMEM = NSTG * STAGE + 256;

constexpr float ASCALE   = 8192.0f;     // exact pow2: adj*ASCALE in (0,1) for fp16
constexpr float ASCALE_I = 1.0f / 8192.0f;

// ---------------------------------------------------------------------------
// Device scratch (allocation-free per harness rules)
// ---------------------------------------------------------------------------
__device__ unsigned short g_bh[HC * NN];    // fts^T fp16 [n][k]
__device__ float g_acc0[NN * HC];           // K-half 0 partial (scaled by 8192)
__device__ float g_acc1[NN * HC];           // K-half 1 partial
__device__ float g_h[NN * HC];              // h1|h2 after bias+PReLU
__device__ float g_part[128 * 64];          // per-64-row-slab colsums of h1*msk
__device__ float g_mskpart[128];            // per-slab msk sums
__device__ float g_wc[64];                  // disc_w @ sigmoid(c)

// ---------------------------------------------------------------------------
// Helpers (baseline PTX only — compute_103 virtual target safe)
// ---------------------------------------------------------------------------
__device__ __forceinline__ uint32_t smem_u32(const void* p) {
    uint32_t r;
    asm("{ .reg .u64 t; cvta.to.shared.u64 t, %1; cvt.u32.u64 %0, t; }"
        : "=r"(r) : "l"(p));
    return r;
}
__device__ __forceinline__ uint32_t pkhf(float lo, float hi) {
    // packed f16x2: low half = f16(lo), high half = f16(hi)
    __half2 h = __floats2half2_rn(lo, hi);
    return *reinterpret_cast<uint32_t*>(&h);
}
__device__ __forceinline__ void sts128(uint32_t addr, uint32_t a, uint32_t b,
                                       uint32_t c, uint32_t d) {
    asm volatile("st.shared.v4.b32 [%0], {%1, %2, %3, %4};"
                 :: "r"(addr), "r"(a), "r"(b), "r"(c), "r"(d) : "memory");
}
__device__ __forceinline__ void ldm4(uint32_t* r, uint32_t addr) {
    asm volatile("ldmatrix.sync.aligned.m8n8.x4.shared.b16 {%0,%1,%2,%3}, [%4];"
                 : "=r"(r[0]), "=r"(r[1]), "=r"(r[2]), "=r"(r[3]) : "r"(addr));
}
__device__ __forceinline__ void mma16816(float* c, const uint32_t* a,
                                         uint32_t b0, uint32_t b1) {
    asm volatile(
        "mma.sync.aligned.m16n8k16.row.col.f32.f16.f16.f32 "
        "{%0,%1,%2,%3}, {%4,%5,%6,%7}, {%8,%9}, {%0,%1,%2,%3};"
        : "+f"(c[0]), "+f"(c[1]), "+f"(c[2]), "+f"(c[3])
        : "r"(a[0]), "r"(a[1]), "r"(a[2]), "r"(a[3]), "r"(b0), "r"(b1));
}

// ---------------------------------------------------------------------------
// Kernel 1: fts = seq@W^T (both seqs); emit fp16 TRANSPOSED [n][k]
// ---------------------------------------------------------------------------
__global__ void __launch_bounds__(128) fts_kernel(
    const float* __restrict__ seq1, const float* __restrict__ seq2,
    const float* __restrict__ fcw) {
    __shared__ float wt[64][64];    // transposed fc_w chunk [f_local][h]
    __shared__ float s1[16][64];
    __shared__ float s2[16][64];

    const int tid = threadIdx.x;
    const int m0 = blockIdx.x * 16;
    const int jh = tid & 63;

    float acc[16];
#pragma unroll
    for (int r = 0; r < 16; ++r) acc[r] = 0.f;

    for (int fc = 0; fc < 4; ++fc) {
        const int f0 = fc * 64;
        __syncthreads();
        {
            const int row = tid & 63, half = tid >> 6;
#pragma unroll
            for (int p = 0; p < 8; ++p) {
                const int c = half * 8 + p;
                float4 v = *(const float4*)&fcw[row * FIN + f0 + c * 4];
                wt[c * 4 + 0][row] = v.x;
                wt[c * 4 + 1][row] = v.y;
                wt[c * 4 + 2][row] = v.z;
                wt[c * 4 + 3][row] = v.w;
            }
        }
#pragma unroll
        for (int p = 0; p < 2; ++p) {
            const int idx = tid + 128 * p;
            const int r = idx >> 4, c4 = idx & 15;
            *(float4*)&s1[r][c4 * 4] = *(const float4*)&seq1[(size_t)(m0 + r) * FIN + f0 + c4 * 4];
            *(float4*)&s2[r][c4 * 4] = *(const float4*)&seq2[(size_t)(m0 + r) * FIN + f0 + c4 * 4];
        }
        __syncthreads();

        const float (*sp)[64] = (tid < 64) ? s1 : s2;
#pragma unroll 4
        for (int f = 0; f < 64; ++f) {
            const float wv = wt[f][jh];
#pragma unroll
            for (int r = 0; r < 16; ++r) acc[r] += sp[r][f] * wv;
        }
    }

    // fp16 pack, transposed store: row = tid (n), cols k = m0..m0+15
#pragma unroll
    for (int r = 0; r < 16; r += 2) {
        const uint32_t h = pkhf(acc[r], acc[r + 1]);
        *(uint32_t*)(g_bh + (size_t)tid * NN + m0 + r) = h;
    }
}

// ---------------------------------------------------------------------------
// Kernel 2 (dominant): single-pass fp16 HMMA GEMM, 3-stage / 1 sync per iter.
// CTA = (mi, kh): rows [mi*128, +128), K-half kh; 8 warps (4M x 2N).
// Computes (8192*adj) @ fts in fp32 accumulate; rescaled in epilogue kernel.
// ---------------------------------------------------------------------------
__global__ void __launch_bounds__(256, 1)
gemm_mma(const float* __restrict__ adj) {
    extern __shared__ char dyn[];
    const uint32_t sbase = (smem_u32(dyn) + 127u) & ~127u;

    const int tid = threadIdx.x;
    const int wid = tid >> 5;
    const int lane = tid & 31;
    const int mi = blockIdx.x >> 1;
    const int kh = blockIdx.x & 1;
    const int m0 = mi * BM;
    const size_t kbase = (size_t)kh * KHALF;

    const int wm = (wid & 3) * 32;      // warp M offset
    const int wn = (wid >> 2) * 64;     // warp N offset

    // producer mapping: thread -> (row 0..127, k-half-of-chunk 0/1)
    const int row = tid & 127;
    const int half = tid >> 7;
    const float* aptr = adj + (size_t)(m0 + row) * NN + kbase + half * 16;
    const unsigned short* bptr = g_bh + (size_t)row * NN + kbase + half * 16;
    const uint32_t a_sts = (uint32_t)(row * ROWB + half * 32);
    const uint32_t b_sts = (uint32_t)(row * ROWB + half * 32);

    // ldmatrix per-lane offsets (validated layout from R4)
    const uint32_t a_ld = (uint32_t)((wm + (lane & 15)) * ROWB + (lane >> 4) * 16);
    const uint32_t b_ld = (uint32_t)((wn + ((lane >> 4) << 3) + (lane & 7)) * ROWB
                                     + ((lane >> 3) & 1) * 16);

    float acc[2][8][4];
#pragma unroll
    for (int i = 0; i < 2; ++i)
#pragma unroll
        for (int j = 0; j < 8; ++j)
#pragma unroll
            for (int q = 0; q < 4; ++q) acc[i][j][q] = 0.f;

    float4 av[2][4];    // double-buffered LDG registers
    uint4  bv[2][2];

    auto LDG = [&](int t, int set) {
        const float4* ap = (const float4*)(aptr + (size_t)t * BKk);
#pragma unroll
        for (int j = 0; j < 4; ++j) av[set][j] = ap[j];
        const uint4* bp = (const uint4*)(bptr + (size_t)t * BKk);
#pragma unroll
        for (int j = 0; j < 2; ++j) bv[set][j] = bp[j];
    };
    auto STS = [&](int t, int set) {
        const uint32_t st = sbase + (t % NSTG) * STAGE;
        uint32_t w[8];
#pragma unroll
        for (int j = 0; j < 4; ++j) {
            w[2 * j]     = pkhf(av[set][j].x * ASCALE, av[set][j].y * ASCALE);
            w[2 * j + 1] = pkhf(av[set][j].z * ASCALE, av[set][j].w * ASCALE);
        }
        sts128(st + OA + a_sts,      w[0], w[1], w[2], w[3]);
        sts128(st + OA + a_sts + 16, w[4], w[5], w[6], w[7]);
        sts128(st + OB + b_sts,      bv[set][0].x, bv[set][0].y, bv[set][0].z, bv[set][0].w);
        sts128(st + OB + b_sts + 16, bv[set][1].x, bv[set][1].y, bv[set][1].z, bv[set][1].w);
    };
    auto COMPUTE = [&](int t) {
        const uint32_t st = sbase + (t % NSTG) * STAGE;
#pragma unroll
        for (int ks = 0; ks < 2; ++ks) {
            uint32_t ah[2][4];
            ldm4(ah[0], st + OA + a_ld + ks * 32);
            ldm4(ah[1], st + OA + a_ld + 16 * ROWB + ks * 32);
#pragma unroll
            for (int jp = 0; jp < 4; ++jp) {
                uint32_t b[4];
                ldm4(b, st + OB + b_ld + jp * (16 * ROWB) + ks * 32);
                mma16816(acc[0][2 * jp],     ah[0], b[0], b[1]);
                mma16816(acc[0][2 * jp + 1], ah[0], b[2], b[3]);
                mma16816(acc[1][2 * jp],     ah[1], b[0], b[1]);
                mma16816(acc[1][2 * jp + 1], ah[1], b[2], b[3]);
            }
        }
    };

    // prologue: chunks 0 and 1 in flight, stage0 filled
    LDG(0, 0);
    LDG(1, 1);
    STS(0, 0);
    __syncthreads();

    int cur = 1;
    for (int t = 0; t < NT; ++t) {
        if (t + 1 < NT) STS(t + 1, cur);        // fill stage (t+1)%3
        if (t + 2 < NT) LDG(t + 2, cur ^ 1);    // prefetch chunk t+2
        COMPUTE(t);
        __syncthreads();
        cur ^= 1;
    }

    // epilogue: write raw (scaled) partials
    float* gacc = (kh ? g_acc1 : g_acc0);
    const int r0 = m0 + wm + (lane >> 2);
    const int cb = wn + (lane & 3) * 2;
#pragma unroll
    for (int i = 0; i < 2; ++i) {
#pragma unroll
        for (int j = 0; j < 8; ++j) {
            const int rr = r0 + i * 16;
            const int col = cb + j * 8;
            *(float2*)&gacc[(size_t)rr * HC + col] =
                make_float2(acc[i][j][0], acc[i][j][1]);
            *(float2*)&gacc[(size_t)(rr + 8) * HC + col] =
                make_float2(acc[i][j][2], acc[i][j][3]);
        }
    }
}

// ---------------------------------------------------------------------------
// Kernel 3: h = PReLU((acc0+acc1)/8192 + bias), fused per-slab colsums of
// h1*msk and msk partials. grid 128 blocks (64 rows each) x 256 threads.
// ---------------------------------------------------------------------------
__global__ void __launch_bounds__(256) epi_colsum(
    const float* __restrict__ bias, const float* __restrict__ alphap,
    const float* __restrict__ msk) {
    __shared__ float sp[2][64];
    __shared__ float sm[64];
    const int b = blockIdx.x, tid = threadIdx.x;
    const int c = tid & 127, rg = tid >> 7;
    const int base = b * 64;
    const float alpha = __ldg(alphap);
    const float bi = __ldg(&bias[c & 63]);

    float csum = 0.f;
#pragma unroll 4
    for (int i = 0; i < 32; ++i) {
        const int n = base + rg + 2 * i;
        const size_t idx = (size_t)n * HC + c;
        float v = (g_acc0[idx] + g_acc1[idx]) * ASCALE_I + bi;
        v = v > 0.f ? v : alpha * v;
        g_h[idx] = v;
        csum += msk[n] * v;     // only meaningful for c<64 (h1)
    }
    if (c < 64) sp[rg][c] = csum;
    if (tid < 64) sm[tid] = msk[base + tid];
    __syncthreads();

    if (tid < 64) g_part[b * 64 + tid] = sp[0][tid] + sp[1][tid];
    if (tid < 32) {
        float m = sm[tid] + sm[tid + 32];
#pragma unroll
        for (int o = 16; o; o >>= 1) m += __shfl_down_sync(0xffffffffu, m, o);
        if (tid == 0) g_mskpart[b] = m;
    }
}

// ---------------------------------------------------------------------------
// Kernel 4: c = sigmoid(colsum/msksum); wc = disc_w @ c
// ---------------------------------------------------------------------------
__global__ void __launch_bounds__(256) make_wc2(const float* __restrict__ disc_w) {
    __shared__ float red[4][64];
    __shared__ float cvec[64];
    __shared__ float smm[128];
    __shared__ float msum_s;
    const int tid = threadIdx.x;
    const int g = tid >> 6, col = tid & 63;

    float s = 0.f;
#pragma unroll
    for (int b = 0; b < 32; ++b) s += g_part[(g * 32 + b) * 64 + col];
    red[g][col] = s;

    if (tid < 128) smm[tid] = g_mskpart[tid];
    __syncthreads();
    if (tid < 32) {
        float m = smm[tid] + smm[tid + 32] + smm[tid + 64] + smm[tid + 96];
#pragma unroll
        for (int o = 16; o; o >>= 1) m += __shfl_down_sync(0xffffffffu, m, o);
        if (tid == 0) msum_s = m;
    }
    __syncthreads();
    if (tid < 64) {
        float cv = (red[0][tid] + red[1][tid] + red[2][tid] + red[3][tid]) / msum_s;
        cvec[tid] = 1.f / (1.f + expf(-cv));
    }
    __syncthreads();

    const int j = tid >> 2, q = tid & 3;
    float r = 0.f;
#pragma unroll
    for (int k = 0; k < 16; ++k) r += disc_w[j * 64 + q * 16 + k] * cvec[q * 16 + k];
    r += __shfl_down_sync(0xffffffffu, r, 2);
    r += __shfl_down_sync(0xffffffffu, r, 1);
    if (q == 0) g_wc[j] = r;
}

// ---------------------------------------------------------------------------
// Kernel 5: out[n] = h1[n,:].wc + b ; out[N+n] = h2[n,:].wc + b
// ---------------------------------------------------------------------------
__global__ void __launch_bounds__(256) scores(const float* __restrict__ db,
                                              float* __restrict__ out) {
    const int warp = threadIdx.x >> 5, lane = threadIdx.x & 31;
    const int n = blockIdx.x * 8 + warp;
    const float2* hp = (const float2*)(g_h + (size_t)n * HC);
    const float2 w2 = ((const float2*)g_wc)[lane];
    const float2 v1 = hp[lane];
    const float2 v2 = hp[32 + lane];
    float s1 = v1.x * w2.x + v1.y * w2.y;
    float s2 = v2.x * w2.x + v2.y * w2.y;
#pragma unroll
    for (int o = 16; o; o >>= 1) {
        s1 += __shfl_down_sync(0xffffffffu, s1, o);
        s2 += __shfl_down_sync(0xffffffffu, s2, o);
    }
    if (lane == 0) {
        const float bb = __ldg(db);
        out[n] = s1 + bb;
        out[NN + n] = s2 + bb;
    }
}

// ---------------------------------------------------------------------------
// Inputs: seq1, seq2, adj, msk, fc_w, gcn_bias, prelu_alpha, disc_w, disc_b
// Output: [1, 2N] float32
// ---------------------------------------------------------------------------
extern "C" void kernel_launch(void* const* d_in, const int* in_sizes, int n_in,
                              void* d_out, int out_size) {
    const float* seq1  = (const float*)d_in[0];
    const float* seq2  = (const float*)d_in[1];
    const float* adj   = (const float*)d_in[2];
    const float* msk   = (const float*)d_in[3];
    const float* fcw   = (const float*)d_in[4];
    const float* gbias = (const float*)d_in[5];
    const float* alpha = (const float*)d_in[6];
    const float* discw = (const float*)d_in[7];
    const float* discb = (const float*)d_in[8];
    float* out = (float*)d_out;

    cudaFuncSetAttribute(gemm_mma, cudaFuncAttributeMaxDynamicSharedMemorySize,
                         DYN_SMEM);

    fts_kernel<<<NN / 16, 128>>>(seq1, seq2, fcw);
    gemm_mma<<<128, 256, DYN_SMEM>>>(adj);
    epi_colsum<<<128, 256>>>(gbias, alpha, msk);
    make_wc2<<<1, 256>>>(discw);
    scores<<<NN / 8, 256>>>(discb, out);
}

// round 6
// speedup vs baseline: 1.3568x; 1.3568x over previous
#include <cuda_runtime.h>
#include <cuda_fp16.h>
#include <cstdint>
#include <cstddef>

// ---------------------------------------------------------------------------
// Problem constants
// ---------------------------------------------------------------------------
constexpr int NN  = 8192;   // nodes
constexpr int FIN = 256;    // input features
constexpr int HC  = 128;    // fused hidden columns (h1 | h2)

// GEMM tiling (single-pass fp16 mma.sync)
constexpr int BM = 128, BN = 128, BKk = 32;
constexpr int KHALF = NN / 2;           // 4096
constexpr int NT = KHALF / BKk;         // 128 iters
constexpr int ROWB = 80;                // padded smem row stride (bytes)
constexpr int OA = 0;
constexpr int OB = BM * ROWB;           // 10240
constexpr int STAGE = OB + BN * ROWB;   // 20480 bytes / stage
constexpr int NSTG = 3;
constexpr int DYN_SMEM = NSTG * STAGE + 256;

constexpr float ASCALE   = 8192.0f;     // exact pow2: adj*ASCALE in (0,1) for fp16
constexpr float ASCALE_I = 1.0f / 8192.0f;

// ---------------------------------------------------------------------------
// Device scratch (allocation-free per harness rules)
// ---------------------------------------------------------------------------
__device__ unsigned short g_bh[HC * NN];    // fts^T fp16 [n][k]
__device__ float g_acc0[NN * HC];           // K-half 0 partial (scaled by 8192)
__device__ float g_acc1[NN * HC];           // K-half 1 partial
__device__ float g_h[NN * HC];              // h1|h2 after bias+PReLU
__device__ float g_part[128 * 64];          // per-64-row-slab colsums of h1*msk
__device__ float g_mskpart[128];            // per-slab msk sums
__device__ float g_wc[64];                  // disc_w @ sigmoid(c)

// ---------------------------------------------------------------------------
// Helpers (baseline PTX only — compute_103 virtual target safe)
// ---------------------------------------------------------------------------
__device__ __forceinline__ uint32_t smem_u32(const void* p) {
    uint32_t r;
    asm("{ .reg .u64 t; cvta.to.shared.u64 t, %1; cvt.u32.u64 %0, t; }"
        : "=r"(r) : "l"(p));
    return r;
}
__device__ __forceinline__ uint32_t pkhf(float lo, float hi) {
    __half2 h = __floats2half2_rn(lo, hi);
    return *reinterpret_cast<uint32_t*>(&h);
}
__device__ __forceinline__ void sts64(uint32_t addr, uint32_t a, uint32_t b) {
    asm volatile("st.shared.v2.b32 [%0], {%1, %2};"
                 :: "r"(addr), "r"(a), "r"(b) : "memory");
}
__device__ __forceinline__ void sts128(uint32_t addr, uint32_t a, uint32_t b,
                                       uint32_t c, uint32_t d) {
    asm volatile("st.shared.v4.b32 [%0], {%1, %2, %3, %4};"
                 :: "r"(addr), "r"(a), "r"(b), "r"(c), "r"(d) : "memory");
}
__device__ __forceinline__ void ldm4(uint32_t* r, uint32_t addr) {
    asm volatile("ldmatrix.sync.aligned.m8n8.x4.shared.b16 {%0,%1,%2,%3}, [%4];"
                 : "=r"(r[0]), "=r"(r[1]), "=r"(r[2]), "=r"(r[3]) : "r"(addr));
}
__device__ __forceinline__ void mma16816(float* c, const uint32_t* a,
                                         uint32_t b0, uint32_t b1) {
    asm volatile(
        "mma.sync.aligned.m16n8k16.row.col.f32.f16.f16.f32 "
        "{%0,%1,%2,%3}, {%4,%5,%6,%7}, {%8,%9}, {%0,%1,%2,%3};"
        : "+f"(c[0]), "+f"(c[1]), "+f"(c[2]), "+f"(c[3])
        : "r"(a[0]), "r"(a[1]), "r"(a[2]), "r"(a[3]), "r"(b0), "r"(b1));
}

// ---------------------------------------------------------------------------
// Kernel 1: fts = seq@W^T (both seqs); emit fp16 TRANSPOSED [n][k]
// ---------------------------------------------------------------------------
__global__ void __launch_bounds__(128) fts_kernel(
    const float* __restrict__ seq1, const float* __restrict__ seq2,
    const float* __restrict__ fcw) {
    __shared__ float wt[64][64];    // transposed fc_w chunk [f_local][h]
    __shared__ float s1[16][64];
    __shared__ float s2[16][64];

    const int tid = threadIdx.x;
    const int m0 = blockIdx.x * 16;
    const int jh = tid & 63;

    float acc[16];
#pragma unroll
    for (int r = 0; r < 16; ++r) acc[r] = 0.f;

    for (int fc = 0; fc < 4; ++fc) {
        const int f0 = fc * 64;
        __syncthreads();
        {
            const int row = tid & 63, half = tid >> 6;
#pragma unroll
            for (int p = 0; p < 8; ++p) {
                const int c = half * 8 + p;
                float4 v = *(const float4*)&fcw[row * FIN + f0 + c * 4];
                wt[c * 4 + 0][row] = v.x;
                wt[c * 4 + 1][row] = v.y;
                wt[c * 4 + 2][row] = v.z;
                wt[c * 4 + 3][row] = v.w;
            }
        }
#pragma unroll
        for (int p = 0; p < 2; ++p) {
            const int idx = tid + 128 * p;
            const int r = idx >> 4, c4 = idx & 15;
            *(float4*)&s1[r][c4 * 4] = *(const float4*)&seq1[(size_t)(m0 + r) * FIN + f0 + c4 * 4];
            *(float4*)&s2[r][c4 * 4] = *(const float4*)&seq2[(size_t)(m0 + r) * FIN + f0 + c4 * 4];
        }
        __syncthreads();

        const float (*sp)[64] = (tid < 64) ? s1 : s2;
#pragma unroll 4
        for (int f = 0; f < 64; ++f) {
            const float wv = wt[f][jh];
#pragma unroll
            for (int r = 0; r < 16; ++r) acc[r] += sp[r][f] * wv;
        }
    }

#pragma unroll
    for (int r = 0; r < 16; r += 2) {
        const uint32_t h = pkhf(acc[r], acc[r + 1]);
        *(uint32_t*)(g_bh + (size_t)tid * NN + m0 + r) = h;
    }
}

// ---------------------------------------------------------------------------
// Kernel 2 (dominant): single-pass fp16 HMMA GEMM, 3-stage / 1 sync per iter.
// COALESCED producers: warp A-LDG touches 4 lines (was 32), B-LDG 8 (was 16).
// CTA = (mi, kh): rows [mi*128, +128), K-half kh; 8 warps (4M x 2N).
// ---------------------------------------------------------------------------
__global__ void __launch_bounds__(256, 1)
gemm_mma(const float* __restrict__ adj) {
    extern __shared__ char dyn[];
    const uint32_t sbase = (smem_u32(dyn) + 127u) & ~127u;

    const int tid = threadIdx.x;
    const int wid = tid >> 5;
    const int lane = tid & 31;
    const int mi = blockIdx.x >> 1;
    const int kh = blockIdx.x & 1;
    const int m0 = mi * BM;
    const size_t kbase = (size_t)kh * KHALF;

    const int wm = (wid & 3) * 32;      // warp M offset
    const int wn = (wid >> 2) * 64;     // warp N offset

    // --- coalesced producer mappings ---
    // A: pass p (0..3): row = p*32 + (tid>>3), 8 lanes cover one 128B row-line
    const int arow = tid >> 3;              // 0..31
    const int acol = (tid & 7) * 4;         // float index 0..28
    const float* aptr = adj + (size_t)(m0 + arow) * NN + kbase + acol;
    const uint32_t a_sts = (uint32_t)(arow * ROWB + (tid & 7) * 8);
    // B: pass p (0..1): row = p*64 + (tid>>2), 4 lanes cover one 64B row
    const int brow = tid >> 2;              // 0..63
    const int bcol = (tid & 3) * 8;         // fp16 index (16B units *8)
    const unsigned short* bptr = g_bh + (size_t)brow * NN + kbase + bcol;
    const uint32_t b_sts = (uint32_t)(brow * ROWB + (tid & 3) * 16);

    // ldmatrix per-lane offsets (layout unchanged from R4/R5)
    const uint32_t a_ld = (uint32_t)((wm + (lane & 15)) * ROWB + (lane >> 4) * 16);
    const uint32_t b_ld = (uint32_t)((wn + ((lane >> 4) << 3) + (lane & 7)) * ROWB
                                     + ((lane >> 3) & 1) * 16);

    float acc[2][8][4];
#pragma unroll
    for (int i = 0; i < 2; ++i)
#pragma unroll
        for (int j = 0; j < 8; ++j)
#pragma unroll
            for (int q = 0; q < 4; ++q) acc[i][j][q] = 0.f;

    float4 av[2][4];    // A: 4 passes (rows +0,+32,+64,+96)
    uint4  bv[2][2];    // B: 2 passes (rows +0,+64)

    auto LDG = [&](int t, int set) {
        const float4* ap = (const float4*)(aptr + (size_t)t * BKk);
#pragma unroll
        for (int p = 0; p < 4; ++p)
            av[set][p] = *(const float4*)((const float*)ap + (size_t)p * 32 * NN);
        const uint4* bp = (const uint4*)(bptr + (size_t)t * BKk);
#pragma unroll
        for (int p = 0; p < 2; ++p)
            bv[set][p] = *(const uint4*)((const unsigned short*)bp + (size_t)p * 64 * NN);
    };
    auto STS = [&](int t, int set) {
        const uint32_t st = sbase + (t % NSTG) * STAGE;
#pragma unroll
        for (int p = 0; p < 4; ++p) {
            uint32_t w0 = pkhf(av[set][p].x * ASCALE, av[set][p].y * ASCALE);
            uint32_t w1 = pkhf(av[set][p].z * ASCALE, av[set][p].w * ASCALE);
            sts64(st + OA + a_sts + p * (32 * ROWB), w0, w1);
        }
#pragma unroll
        for (int p = 0; p < 2; ++p)
            sts128(st + OB + b_sts + p * (64 * ROWB),
                   bv[set][p].x, bv[set][p].y, bv[set][p].z, bv[set][p].w);
    };
    auto COMPUTE = [&](int t) {
        const uint32_t st = sbase + (t % NSTG) * STAGE;
#pragma unroll
        for (int ks = 0; ks < 2; ++ks) {
            uint32_t ah[2][4];
            ldm4(ah[0], st + OA + a_ld + ks * 32);
            ldm4(ah[1], st + OA + a_ld + 16 * ROWB + ks * 32);
#pragma unroll
            for (int jp = 0; jp < 4; ++jp) {
                uint32_t b[4];
                ldm4(b, st + OB + b_ld + jp * (16 * ROWB) + ks * 32);
                mma16816(acc[0][2 * jp],     ah[0], b[0], b[1]);
                mma16816(acc[0][2 * jp + 1], ah[0], b[2], b[3]);
                mma16816(acc[1][2 * jp],     ah[1], b[0], b[1]);
                mma16816(acc[1][2 * jp + 1], ah[1], b[2], b[3]);
            }
        }
    };

    // prologue: chunks 0 and 1 in flight, stage0 filled
    LDG(0, 0);
    LDG(1, 1);
    STS(0, 0);
    __syncthreads();

    int cur = 1;
    for (int t = 0; t < NT; ++t) {
        if (t + 1 < NT) STS(t + 1, cur);        // fill stage (t+1)%3
        if (t + 2 < NT) LDG(t + 2, cur ^ 1);    // prefetch chunk t+2
        COMPUTE(t);
        __syncthreads();
        cur ^= 1;
    }

    // epilogue: write raw (scaled) partials
    float* gacc = (kh ? g_acc1 : g_acc0);
    const int r0 = m0 + wm + (lane >> 2);
    const int cb = wn + (lane & 3) * 2;
#pragma unroll
    for (int i = 0; i < 2; ++i) {
#pragma unroll
        for (int j = 0; j < 8; ++j) {
            const int rr = r0 + i * 16;
            const int col = cb + j * 8;
            *(float2*)&gacc[(size_t)rr * HC + col] =
                make_float2(acc[i][j][0], acc[i][j][1]);
            *(float2*)&gacc[(size_t)(rr + 8) * HC + col] =
                make_float2(acc[i][j][2], acc[i][j][3]);
        }
    }
}

// ---------------------------------------------------------------------------
// Kernel 3: h = PReLU((acc0+acc1)/8192 + bias), fused per-slab colsums of
// h1*msk and msk partials. grid 128 blocks (64 rows each) x 256 threads.
// ---------------------------------------------------------------------------
__global__ void __launch_bounds__(256) epi_colsum(
    const float* __restrict__ bias, const float* __restrict__ alphap,
    const float* __restrict__ msk) {
    __shared__ float sp[2][64];
    __shared__ float sm[64];
    const int b = blockIdx.x, tid = threadIdx.x;
    const int c = tid & 127, rg = tid >> 7;
    const int base = b * 64;
    const float alpha = __ldg(alphap);
    const float bi = __ldg(&bias[c & 63]);

    float csum = 0.f;
#pragma unroll 4
    for (int i = 0; i < 32; ++i) {
        const int n = base + rg + 2 * i;
        const size_t idx = (size_t)n * HC + c;
        float v = (g_acc0[idx] + g_acc1[idx]) * ASCALE_I + bi;
        v = v > 0.f ? v : alpha * v;
        g_h[idx] = v;
        csum += msk[n] * v;     // only meaningful for c<64 (h1)
    }
    if (c < 64) sp[rg][c] = csum;
    if (tid < 64) sm[tid] = msk[base + tid];
    __syncthreads();

    if (tid < 64) g_part[b * 64 + tid] = sp[0][tid] + sp[1][tid];
    if (tid < 32) {
        float m = sm[tid] + sm[tid + 32];
#pragma unroll
        for (int o = 16; o; o >>= 1) m += __shfl_down_sync(0xffffffffu, m, o);
        if (tid == 0) g_mskpart[b] = m;
    }
}

// ---------------------------------------------------------------------------
// Kernel 4: c = sigmoid(colsum/msksum); wc = disc_w @ c
// ---------------------------------------------------------------------------
__global__ void __launch_bounds__(256) make_wc2(const float* __restrict__ disc_w) {
    __shared__ float red[4][64];
    __shared__ float cvec[64];
    __shared__ float smm[128];
    __shared__ float msum_s;
    const int tid = threadIdx.x;
    const int g = tid >> 6, col = tid & 63;

    float s = 0.f;
#pragma unroll
    for (int b = 0; b < 32; ++b) s += g_part[(g * 32 + b) * 64 + col];
    red[g][col] = s;

    if (tid < 128) smm[tid] = g_mskpart[tid];
    __syncthreads();
    if (tid < 32) {
        float m = smm[tid] + smm[tid + 32] + smm[tid + 64] + smm[tid + 96];
#pragma unroll
        for (int o = 16; o; o >>= 1) m += __shfl_down_sync(0xffffffffu, m, o);
        if (tid == 0) msum_s = m;
    }
    __syncthreads();
    if (tid < 64) {
        float cv = (red[0][tid] + red[1][tid] + red[2][tid] + red[3][tid]) / msum_s;
        cvec[tid] = 1.f / (1.f + expf(-cv));
    }
    __syncthreads();

    const int j = tid >> 2, q = tid & 3;
    float r = 0.f;
#pragma unroll
    for (int k = 0; k < 16; ++k) r += disc_w[j * 64 + q * 16 + k] * cvec[q * 16 + k];
    r += __shfl_down_sync(0xffffffffu, r, 2);
    r += __shfl_down_sync(0xffffffffu, r, 1);
    if (q == 0) g_wc[j] = r;
}

// ---------------------------------------------------------------------------
// Kernel 5: out[n] = h1[n,:].wc + b ; out[N+n] = h2[n,:].wc + b
// ---------------------------------------------------------------------------
__global__ void __launch_bounds__(256) scores(const float* __restrict__ db,
                                              float* __restrict__ out) {
    const int warp = threadIdx.x >> 5, lane = threadIdx.x & 31;
    const int n = blockIdx.x * 8 + warp;
    const float2* hp = (const float2*)(g_h + (size_t)n * HC);
    const float2 w2 = ((const float2*)g_wc)[lane];
    const float2 v1 = hp[lane];
    const float2 v2 = hp[32 + lane];
    float s1 = v1.x * w2.x + v1.y * w2.y;
    float s2 = v2.x * w2.x + v2.y * w2.y;
#pragma unroll
    for (int o = 16; o; o >>= 1) {
        s1 += __shfl_down_sync(0xffffffffu, s1, o);
        s2 += __shfl_down_sync(0xffffffffu, s2, o);
    }
    if (lane == 0) {
        const float bb = __ldg(db);
        out[n] = s1 + bb;
        out[NN + n] = s2 + bb;
    }
}

// ---------------------------------------------------------------------------
// Inputs: seq1, seq2, adj, msk, fc_w, gcn_bias, prelu_alpha, disc_w, disc_b
// Output: [1, 2N] float32
// ---------------------------------------------------------------------------
extern "C" void kernel_launch(void* const* d_in, const int* in_sizes, int n_in,
                              void* d_out, int out_size) {
    const float* seq1  = (const float*)d_in[0];
    const float* seq2  = (const float*)d_in[1];
    const float* adj   = (const float*)d_in[2];
    const float* msk   = (const float*)d_in[3];
    const float* fcw   = (const float*)d_in[4];
    const float* gbias = (const float*)d_in[5];
    const float* alpha = (const float*)d_in[6];
    const float* discw = (const float*)d_in[7];
    const float* discb = (const float*)d_in[8];
    float* out = (float*)d_out;

    cudaFuncSetAttribute(gemm_mma, cudaFuncAttributeMaxDynamicSharedMemorySize,
                         DYN_SMEM);

    fts_kernel<<<NN / 16, 128>>>(seq1, seq2, fcw);
    gemm_mma<<<128, 256, DYN_SMEM>>>(adj);
    epi_colsum<<<128, 256>>>(gbias, alpha, msk);
    make_wc2<<<1, 256>>>(discw);
    scores<<<NN / 8, 256>>>(discb, out);
}

// round 7
// speedup vs baseline: 2.1706x; 1.5998x over previous
#include <cuda_runtime.h>
#include <cuda_fp16.h>
#include <cstdint>
#include <cstddef>

// ---------------------------------------------------------------------------
// Problem constants
// ---------------------------------------------------------------------------
constexpr int NN  = 8192;   // nodes
constexpr int FIN = 256;    // input features
constexpr int HC  = 128;    // fused hidden columns (h1 | h2)

// GEMM tiling (single-pass fp16 mma.sync)
constexpr int BM = 128, BN = 128, BKk = 32;
constexpr int KHALF = NN / 2;           // 4096
constexpr int NT = KHALF / BKk;         // 128 iters
constexpr int ROWB = 80;                // padded smem row stride (bytes)
constexpr int OA = 0;
constexpr int OB = BM * ROWB;           // 10240
constexpr int STAGE = OB + BN * ROWB;   // 20480 bytes / stage
constexpr int NSTG = 3;
constexpr int DYN_SMEM = NSTG * STAGE + 256;

constexpr float ASCALE   = 8192.0f;     // exact pow2: adj*ASCALE in (0,1) for fp16
constexpr float ASCALE_I = 1.0f / 8192.0f;

// ---------------------------------------------------------------------------
// Device scratch (allocation-free per harness rules)
// ---------------------------------------------------------------------------
__device__ unsigned short g_bh[HC * NN];    // fts^T fp16 [n][k]
__device__ float g_acc0[NN * HC];           // K-half 0 partial (scaled by 8192)
__device__ float g_acc1[NN * HC];           // K-half 1 partial
__device__ float g_h[NN * HC];              // h1|h2 after bias+PReLU
__device__ float g_part[128 * 64];          // per-64-row-slab colsums of h1*msk
__device__ float g_mskpart[128];            // per-slab msk sums
__device__ float g_wc[64];                  // disc_w @ sigmoid(c)

// ---------------------------------------------------------------------------
// Helpers (baseline PTX only — compute_103 virtual target safe)
// ---------------------------------------------------------------------------
__device__ __forceinline__ uint32_t smem_u32(const void* p) {
    uint32_t r;
    asm("{ .reg .u64 t; cvta.to.shared.u64 t, %1; cvt.u32.u64 %0, t; }"
        : "=r"(r) : "l"(p));
    return r;
}
__device__ __forceinline__ uint32_t pkhf(float lo, float hi) {
    __half2 h = __floats2half2_rn(lo, hi);
    return *reinterpret_cast<uint32_t*>(&h);
}
__device__ __forceinline__ void sts64(uint32_t addr, uint32_t a, uint32_t b) {
    asm volatile("st.shared.v2.b32 [%0], {%1, %2};"
                 :: "r"(addr), "r"(a), "r"(b) : "memory");
}
__device__ __forceinline__ void ldm4(uint32_t* r, uint32_t addr) {
    asm volatile("ldmatrix.sync.aligned.m8n8.x4.shared.b16 {%0,%1,%2,%3}, [%4];"
                 : "=r"(r[0]), "=r"(r[1]), "=r"(r[2]), "=r"(r[3]) : "r"(addr));
}
__device__ __forceinline__ void mma16816(float* c, const uint32_t* a,
                                         uint32_t b0, uint32_t b1) {
    asm volatile(
        "mma.sync.aligned.m16n8k16.row.col.f32.f16.f16.f32 "
        "{%0,%1,%2,%3}, {%4,%5,%6,%7}, {%8,%9}, {%0,%1,%2,%3};"
        : "+f"(c[0]), "+f"(c[1]), "+f"(c[2]), "+f"(c[3])
        : "r"(a[0]), "r"(a[1]), "r"(a[2]), "r"(a[3]), "r"(b0), "r"(b1));
}
__device__ __forceinline__ void cpa16(uint32_t dst, const void* src) {
    asm volatile("cp.async.cg.shared.global [%0], [%1], 16;"
                 :: "r"(dst), "l"(src));
}
__device__ __forceinline__ void cp_commit() {
    asm volatile("cp.async.commit_group;" ::: "memory");
}
__device__ __forceinline__ void cp_wait2() {
    asm volatile("cp.async.wait_group 2;" ::: "memory");
}

// ---------------------------------------------------------------------------
// Kernel 1: fts = seq@W^T (both seqs); emit fp16 TRANSPOSED [n][k]
// ---------------------------------------------------------------------------
__global__ void __launch_bounds__(128) fts_kernel(
    const float* __restrict__ seq1, const float* __restrict__ seq2,
    const float* __restrict__ fcw) {
    __shared__ float wt[64][64];    // transposed fc_w chunk [f_local][h]
    __shared__ float s1[16][64];
    __shared__ float s2[16][64];

    const int tid = threadIdx.x;
    const int m0 = blockIdx.x * 16;
    const int jh = tid & 63;

    float acc[16];
#pragma unroll
    for (int r = 0; r < 16; ++r) acc[r] = 0.f;

    for (int fc = 0; fc < 4; ++fc) {
        const int f0 = fc * 64;
        __syncthreads();
        {
            const int row = tid & 63, half = tid >> 6;
#pragma unroll
            for (int p = 0; p < 8; ++p) {
                const int c = half * 8 + p;
                float4 v = *(const float4*)&fcw[row * FIN + f0 + c * 4];
                wt[c * 4 + 0][row] = v.x;
                wt[c * 4 + 1][row] = v.y;
                wt[c * 4 + 2][row] = v.z;
                wt[c * 4 + 3][row] = v.w;
            }
        }
#pragma unroll
        for (int p = 0; p < 2; ++p) {
            const int idx = tid + 128 * p;
            const int r = idx >> 4, c4 = idx & 15;
            *(float4*)&s1[r][c4 * 4] = *(const float4*)&seq1[(size_t)(m0 + r) * FIN + f0 + c4 * 4];
            *(float4*)&s2[r][c4 * 4] = *(const float4*)&seq2[(size_t)(m0 + r) * FIN + f0 + c4 * 4];
        }
        __syncthreads();

        const float (*sp)[64] = (tid < 64) ? s1 : s2;
#pragma unroll 4
        for (int f = 0; f < 64; ++f) {
            const float wv = wt[f][jh];
#pragma unroll
            for (int r = 0; r < 16; ++r) acc[r] += sp[r][f] * wv;
        }
    }

#pragma unroll
    for (int r = 0; r < 16; r += 2) {
        const uint32_t h = pkhf(acc[r], acc[r + 1]);
        *(uint32_t*)(g_bh + (size_t)tid * NN + m0 + r) = h;
    }
}

// ---------------------------------------------------------------------------
// Kernel 2 (dominant): single-pass fp16 HMMA GEMM.
// Compute-first loop: BCP(t+2) -> ALDG(t+2) -> COMPUTE(t) -> ASTS(t+1) -> sync.
// B flows through cp.async (no conversion); A through registers (f32->f16).
// CTA = (mi, kh): rows [mi*128, +128), K-half kh; 8 warps (4M x 2N).
// ---------------------------------------------------------------------------
__global__ void __launch_bounds__(256, 1)
gemm_mma(const float* __restrict__ adj) {
    extern __shared__ char dyn[];
    const uint32_t sbase = (smem_u32(dyn) + 127u) & ~127u;

    const int tid = threadIdx.x;
    const int wid = tid >> 5;
    const int lane = tid & 31;
    const int mi = blockIdx.x >> 1;
    const int kh = blockIdx.x & 1;
    const int m0 = mi * BM;
    const size_t kbase = (size_t)kh * KHALF;

    const int wm = (wid & 3) * 32;      // warp M offset
    const int wn = (wid >> 2) * 64;     // warp N offset

    // --- coalesced producer mappings ---
    // A: pass p (0..3): row = p*32 + (tid>>3), 8 lanes cover one 128B row-line
    const int arow = tid >> 3;              // 0..31
    const int acol = (tid & 7) * 4;         // float index
    const float* aptr = adj + (size_t)(m0 + arow) * NN + kbase + acol;
    const uint32_t a_sts = (uint32_t)(arow * ROWB + (tid & 7) * 8);
    // B: pass p (0..1): row = p*64 + (tid>>2), 4 lanes cover one 64B row
    const int brow = tid >> 2;              // 0..63
    const int bcol = (tid & 3) * 8;         // fp16 index
    const unsigned short* bptr = g_bh + (size_t)brow * NN + kbase + bcol;
    const uint32_t b_sts = (uint32_t)(brow * ROWB + (tid & 3) * 16);

    // ldmatrix per-lane offsets (layout validated R4-R6)
    const uint32_t a_ld = (uint32_t)((wm + (lane & 15)) * ROWB + (lane >> 4) * 16);
    const uint32_t b_ld = (uint32_t)((wn + ((lane >> 4) << 3) + (lane & 7)) * ROWB
                                     + ((lane >> 3) & 1) * 16);

    float acc[2][8][4];
#pragma unroll
    for (int i = 0; i < 2; ++i)
#pragma unroll
        for (int j = 0; j < 8; ++j)
#pragma unroll
            for (int q = 0; q < 4; ++q) acc[i][j][q] = 0.f;

    float4 av[2][4];    // A double-buffered LDG registers (rows +0,+32,+64,+96)

    auto BCP = [&](int t) {     // cp.async B chunk t into stage t%NSTG
        const uint32_t st = sbase + (t % NSTG) * STAGE;
        const unsigned short* bp = bptr + (size_t)t * BKk;
#pragma unroll
        for (int p = 0; p < 2; ++p)
            cpa16(st + OB + b_sts + p * (64 * ROWB), bp + (size_t)p * 64 * NN);
    };
    auto ALDG = [&](int t, int set) {
        const float* ap = aptr + (size_t)t * BKk;
#pragma unroll
        for (int p = 0; p < 4; ++p)
            av[set][p] = *(const float4*)(ap + (size_t)p * 32 * NN);
    };
    auto ASTS = [&](int t, int set) {
        const uint32_t st = sbase + (t % NSTG) * STAGE;
#pragma unroll
        for (int p = 0; p < 4; ++p) {
            uint32_t w0 = pkhf(av[set][p].x * ASCALE, av[set][p].y * ASCALE);
            uint32_t w1 = pkhf(av[set][p].z * ASCALE, av[set][p].w * ASCALE);
            sts64(st + OA + a_sts + p * (32 * ROWB), w0, w1);
        }
    };
    auto COMPUTE = [&](int t) {
        const uint32_t st = sbase + (t % NSTG) * STAGE;
#pragma unroll
        for (int ks = 0; ks < 2; ++ks) {
            uint32_t ah[2][4];
            ldm4(ah[0], st + OA + a_ld + ks * 32);
            ldm4(ah[1], st + OA + a_ld + 16 * ROWB + ks * 32);
#pragma unroll
            for (int jp = 0; jp < 4; ++jp) {
                uint32_t b[4];
                ldm4(b, st + OB + b_ld + jp * (16 * ROWB) + ks * 32);
                mma16816(acc[0][2 * jp],     ah[0], b[0], b[1]);
                mma16816(acc[0][2 * jp + 1], ah[0], b[2], b[3]);
                mma16816(acc[1][2 * jp],     ah[1], b[0], b[1]);
                mma16816(acc[1][2 * jp + 1], ah[1], b[2], b[3]);
            }
        }
    };

    // prologue: B chunks 0,1 in flight (1 group each), A chunks 0,1 in regs,
    // A stage0 stored.
    BCP(0); cp_commit();
    BCP(1); cp_commit();
    ALDG(0, 0);
    ALDG(1, 1);
    ASTS(0, 0);
    __syncthreads();

    int cur = 1;
    for (int t = 0; t < NT; ++t) {
        if (t + 2 < NT) BCP(t + 2);
        cp_commit();                            // uniform commit (may be empty)
        if (t + 2 < NT) ALDG(t + 2, cur ^ 1);
        cp_wait2();                             // B of stage t resident
        COMPUTE(t);
        if (t + 1 < NT) ASTS(t + 1, cur);
        __syncthreads();
        cur ^= 1;
    }

    // epilogue: write raw (scaled) partials
    float* gacc = (kh ? g_acc1 : g_acc0);
    const int r0 = m0 + wm + (lane >> 2);
    const int cb = wn + (lane & 3) * 2;
#pragma unroll
    for (int i = 0; i < 2; ++i) {
#pragma unroll
        for (int j = 0; j < 8; ++j) {
            const int rr = r0 + i * 16;
            const int col = cb + j * 8;
            *(float2*)&gacc[(size_t)rr * HC + col] =
                make_float2(acc[i][j][0], acc[i][j][1]);
            *(float2*)&gacc[(size_t)(rr + 8) * HC + col] =
                make_float2(acc[i][j][2], acc[i][j][3]);
        }
    }
}

// ---------------------------------------------------------------------------
// Kernel 3: h = PReLU((acc0+acc1)/8192 + bias), fused per-slab colsums of
// h1*msk and msk partials. grid 128 blocks (64 rows each) x 256 threads.
// ---------------------------------------------------------------------------
__global__ void __launch_bounds__(256) epi_colsum(
    const float* __restrict__ bias, const float* __restrict__ alphap,
    const float* __restrict__ msk) {
    __shared__ float sp[2][64];
    __shared__ float sm[64];
    const int b = blockIdx.x, tid = threadIdx.x;
    const int c = tid & 127, rg = tid >> 7;
    const int base = b * 64;
    const float alpha = __ldg(alphap);
    const float bi = __ldg(&bias[c & 63]);

    float csum = 0.f;
#pragma unroll 4
    for (int i = 0; i < 32; ++i) {
        const int n = base + rg + 2 * i;
        const size_t idx = (size_t)n * HC + c;
        float v = (g_acc0[idx] + g_acc1[idx]) * ASCALE_I + bi;
        v = v > 0.f ? v : alpha * v;
        g_h[idx] = v;
        csum += msk[n] * v;     // only meaningful for c<64 (h1)
    }
    if (c < 64) sp[rg][c] = csum;
    if (tid < 64) sm[tid] = msk[base + tid];
    __syncthreads();

    if (tid < 64) g_part[b * 64 + tid] = sp[0][tid] + sp[1][tid];
    if (tid < 32) {
        float m = sm[tid] + sm[tid + 32];
#pragma unroll
        for (int o = 16; o; o >>= 1) m += __shfl_down_sync(0xffffffffu, m, o);
        if (tid == 0) g_mskpart[b] = m;
    }
}

// ---------------------------------------------------------------------------
// Kernel 4: c = sigmoid(colsum/msksum); wc = disc_w @ c
// ---------------------------------------------------------------------------
__global__ void __launch_bounds__(256) make_wc2(const float* __restrict__ disc_w) {
    __shared__ float red[4][64];
    __shared__ float cvec[64];
    __shared__ float smm[128];
    __shared__ float msum_s;
    const int tid = threadIdx.x;
    const int g = tid >> 6, col = tid & 63;

    float s = 0.f;
#pragma unroll
    for (int b = 0; b < 32; ++b) s += g_part[(g * 32 + b) * 64 + col];
    red[g][col] = s;

    if (tid < 128) smm[tid] = g_mskpart[tid];
    __syncthreads();
    if (tid < 32) {
        float m = smm[tid] + smm[tid + 32] + smm[tid + 64] + smm[tid + 96];
#pragma unroll
        for (int o = 16; o; o >>= 1) m += __shfl_down_sync(0xffffffffu, m, o);
        if (tid == 0) msum_s = m;
    }
    __syncthreads();
    if (tid < 64) {
        float cv = (red[0][tid] + red[1][tid] + red[2][tid] + red[3][tid]) / msum_s;
        cvec[tid] = 1.f / (1.f + expf(-cv));
    }
    __syncthreads();

    const int j = tid >> 2, q = tid & 3;
    float r = 0.f;
#pragma unroll
    for (int k = 0; k < 16; ++k) r += disc_w[j * 64 + q * 16 + k] * cvec[q * 16 + k];
    r += __shfl_down_sync(0xffffffffu, r, 2);
    r += __shfl_down_sync(0xffffffffu, r, 1);
    if (q == 0) g_wc[j] = r;
}

// ---------------------------------------------------------------------------
// Kernel 5: out[n] = h1[n,:].wc + b ; out[N+n] = h2[n,:].wc + b
// ---------------------------------------------------------------------------
__global__ void __launch_bounds__(256) scores(const float* __restrict__ db,
                                              float* __restrict__ out) {
    const int warp = threadIdx.x >> 5, lane = threadIdx.x & 31;
    const int n = blockIdx.x * 8 + warp;
    const float2* hp = (const float2*)(g_h + (size_t)n * HC);
    const float2 w2 = ((const float2*)g_wc)[lane];
    const float2 v1 = hp[lane];
    const float2 v2 = hp[32 + lane];
    float s1 = v1.x * w2.x + v1.y * w2.y;
    float s2 = v2.x * w2.x + v2.y * w2.y;
#pragma unroll
    for (int o = 16; o; o >>= 1) {
        s1 += __shfl_down_sync(0xffffffffu, s1, o);
        s2 += __shfl_down_sync(0xffffffffu, s2, o);
    }
    if (lane == 0) {
        const float bb = __ldg(db);
        out[n] = s1 + bb;
        out[NN + n] = s2 + bb;
    }
}

// ---------------------------------------------------------------------------
// Inputs: seq1, seq2, adj, msk, fc_w, gcn_bias, prelu_alpha, disc_w, disc_b
// Output: [1, 2N] float32
// ---------------------------------------------------------------------------
extern "C" void kernel_launch(void* const* d_in, const int* in_sizes, int n_in,
                              void* d_out, int out_size) {
    const float* seq1  = (const float*)d_in[0];
    const float* seq2  = (const float*)d_in[1];
    const float* adj   = (const float*)d_in[2];
    const float* msk   = (const float*)d_in[3];
    const float* fcw   = (const float*)d_in[4];
    const float* gbias = (const float*)d_in[5];
    const float* alpha = (const float*)d_in[6];
    const float* discw = (const float*)d_in[7];
    const float* discb = (const float*)d_in[8];
    float* out = (float*)d_out;

    cudaFuncSetAttribute(gemm_mma, cudaFuncAttributeMaxDynamicSharedMemorySize,
                         DYN_SMEM);

    fts_kernel<<<NN / 16, 128>>>(seq1, seq2, fcw);
    gemm_mma<<<128, 256, DYN_SMEM>>>(adj);
    epi_colsum<<<128, 256>>>(gbias, alpha, msk);
    make_wc2<<<1, 256>>>(discw);
    scores<<<NN / 8, 256>>>(discb, out);
}

// round 9
// speedup vs baseline: 2.2667x; 1.0443x over previous
#include <cuda_runtime.h>
#include <cuda_fp16.h>
#include <cstdint>
#include <cstddef>

// ---------------------------------------------------------------------------
// Problem constants
// ---------------------------------------------------------------------------
constexpr int NN  = 8192;   // nodes
constexpr int FIN = 256;    // input features
constexpr int HC  = 128;    // fused hidden columns (h1 | h2)

// GEMM tiling (single-pass fp16 mma.sync), BM=64 for 2 CTAs/SM
constexpr int BM = 64, BN = 128, BKk = 32;
constexpr int KHALF = NN / 2;           // 4096
constexpr int NT = KHALF / BKk;         // 128 iters
constexpr int ROWB = 80;                // padded smem row stride (bytes)
constexpr int OA = 0;
constexpr int OB = BM * ROWB;           // 5120
constexpr int STAGE = OB + BN * ROWB;   // 15360 bytes / stage
constexpr int NSTG = 3;
constexpr int DYN_SMEM = NSTG * STAGE + 256;

constexpr float ASCALE   = 8192.0f;     // exact pow2: adj*ASCALE in (0,1) for fp16
constexpr float ASCALE_I = 1.0f / 8192.0f;

// ---------------------------------------------------------------------------
// Device scratch (allocation-free per harness rules)
// ---------------------------------------------------------------------------
__device__ unsigned short g_bh[HC * NN];    // fts^T fp16 [n][k]
__device__ float g_acc0[NN * HC];           // K-half 0 partial (scaled by 8192)
__device__ float g_acc1[NN * HC];           // K-half 1 partial
__device__ float g_h[NN * HC];              // h1|h2 after bias+PReLU
__device__ float g_part[128 * 64];          // per-64-row-slab colsums of h1*msk
__device__ float g_mskpart[128];            // per-slab msk sums
__device__ float g_wc[64];                  // disc_w @ sigmoid(c)

// ---------------------------------------------------------------------------
// Helpers (baseline PTX only — compute_103 virtual target safe)
// ---------------------------------------------------------------------------
__device__ __forceinline__ uint32_t smem_u32(const void* p) {
    uint32_t r;
    asm("{ .reg .u64 t; cvta.to.shared.u64 t, %1; cvt.u32.u64 %0, t; }"
        : "=r"(r) : "l"(p));
    return r;
}
__device__ __forceinline__ uint32_t pkhf(float lo, float hi) {
    __half2 h = __floats2half2_rn(lo, hi);
    return *reinterpret_cast<uint32_t*>(&h);
}
__device__ __forceinline__ void sts64(uint32_t addr, uint32_t a, uint32_t b) {
    asm volatile("st.shared.v2.b32 [%0], {%1, %2};"
                 :: "r"(addr), "r"(a), "r"(b) : "memory");
}
__device__ __forceinline__ void ldm4(uint32_t* r, uint32_t addr) {
    asm volatile("ldmatrix.sync.aligned.m8n8.x4.shared.b16 {%0,%1,%2,%3}, [%4];"
                 : "=r"(r[0]), "=r"(r[1]), "=r"(r[2]), "=r"(r[3]) : "r"(addr));
}
__device__ __forceinline__ void mma16816(float* c, const uint32_t* a,
                                         uint32_t b0, uint32_t b1) {
    asm volatile(
        "mma.sync.aligned.m16n8k16.row.col.f32.f16.f16.f32 "
        "{%0,%1,%2,%3}, {%4,%5,%6,%7}, {%8,%9}, {%0,%1,%2,%3};"
        : "+f"(c[0]), "+f"(c[1]), "+f"(c[2]), "+f"(c[3])
        : "r"(a[0]), "r"(a[1]), "r"(a[2]), "r"(a[3]), "r"(b0), "r"(b1));
}
__device__ __forceinline__ void cpa16(uint32_t dst, const void* src) {
    asm volatile("cp.async.cg.shared.global [%0], [%1], 16;"
                 :: "r"(dst), "l"(src));
}
__device__ __forceinline__ void cp_commit() {
    asm volatile("cp.async.commit_group;" ::: "memory");
}
__device__ __forceinline__ void cp_wait1() {
    asm volatile("cp.async.wait_group 1;" ::: "memory");
}

// ---------------------------------------------------------------------------
// Kernel 1: fts = seq@W^T (both seqs); emit fp16 TRANSPOSED [n][k]
// ---------------------------------------------------------------------------
__global__ void __launch_bounds__(128) fts_kernel(
    const float* __restrict__ seq1, const float* __restrict__ seq2,
    const float* __restrict__ fcw) {
    __shared__ float wt[64][64];    // transposed fc_w chunk [f_local][h]
    __shared__ float s1[16][64];
    __shared__ float s2[16][64];

    const int tid = threadIdx.x;
    const int m0 = blockIdx.x * 16;
    const int jh = tid & 63;

    float acc[16];
#pragma unroll
    for (int r = 0; r < 16; ++r) acc[r] = 0.f;

    for (int fc = 0; fc < 4; ++fc) {
        const int f0 = fc * 64;
        __syncthreads();
        {
            const int row = tid & 63, half = tid >> 6;
#pragma unroll
            for (int p = 0; p < 8; ++p) {
                const int c = half * 8 + p;
                float4 v = *(const float4*)&fcw[row * FIN + f0 + c * 4];
                wt[c * 4 + 0][row] = v.x;
                wt[c * 4 + 1][row] = v.y;
                wt[c * 4 + 2][row] = v.z;
                wt[c * 4 + 3][row] = v.w;
            }
        }
#pragma unroll
        for (int p = 0; p < 2; ++p) {
            const int idx = tid + 128 * p;
            const int r = idx >> 4, c4 = idx & 15;
            *(float4*)&s1[r][c4 * 4] = *(const float4*)&seq1[(size_t)(m0 + r) * FIN + f0 + c4 * 4];
            *(float4*)&s2[r][c4 * 4] = *(const float4*)&seq2[(size_t)(m0 + r) * FIN + f0 + c4 * 4];
        }
        __syncthreads();

        const float (*sp)[64] = (tid < 64) ? s1 : s2;
#pragma unroll 4
        for (int f = 0; f < 64; ++f) {
            const float wv = wt[f][jh];
#pragma unroll
            for (int r = 0; r < 16; ++r) acc[r] += sp[r][f] * wv;
        }
    }

#pragma unroll
    for (int r = 0; r < 16; r += 2) {
        const uint32_t h = pkhf(acc[r], acc[r + 1]);
        *(uint32_t*)(g_bh + (size_t)tid * NN + m0 + r) = h;
    }
}

// ---------------------------------------------------------------------------
// Kernel 2 (dominant): single-pass fp16 HMMA GEMM, BM=64, 2 CTAs/SM.
// SOUND pipeline: cp.async wait is BEFORE the barrier so the barrier
// publishes completed copies to all threads (fixes R8 cross-thread race).
// Per iter: BCP(t+2);commit -> ALDG(t+2) -> COMPUTE(t) -> ASTS(t+1)
//           -> cp_wait1 -> sync.
// CTA = (mi, kh): rows [mi*64, +64), K-half kh; 8 warps (2M x 4N), 32x32/warp.
// ---------------------------------------------------------------------------
__global__ void __launch_bounds__(256, 2)
gemm_mma(const float* __restrict__ adj) {
    extern __shared__ char dyn[];
    const uint32_t sbase = (smem_u32(dyn) + 127u) & ~127u;

    const int tid = threadIdx.x;
    const int wid = tid >> 5;
    const int lane = tid & 31;
    const int mi = blockIdx.x >> 1;
    const int kh = blockIdx.x & 1;
    const int m0 = mi * BM;
    const size_t kbase = (size_t)kh * KHALF;

    const int wm = (wid & 1) * 32;      // warp M offset (0/32)
    const int wn = (wid >> 1) * 32;     // warp N offset (0..96)

    // --- coalesced producer mappings ---
    // A: pass p (0..1): row = p*32 + (tid>>3), 8 lanes cover one 128B row-line
    const int arow = tid >> 3;              // 0..31
    const float* aptr = adj + (size_t)(m0 + arow) * NN + kbase + (tid & 7) * 4;
    const uint32_t a_sts = (uint32_t)(arow * ROWB + (tid & 7) * 8);
    // B: pass p (0..1): row = p*64 + (tid>>2), 4 lanes cover one 64B row
    const int brow = tid >> 2;              // 0..63
    const unsigned short* bptr = g_bh + (size_t)brow * NN + kbase + (tid & 3) * 8;
    const uint32_t b_sts = (uint32_t)(brow * ROWB + (tid & 3) * 16);

    // ldmatrix per-lane offsets (layout validated R4-R7)
    const uint32_t a_ld = (uint32_t)((wm + (lane & 15)) * ROWB + (lane >> 4) * 16);
    const uint32_t b_ld = (uint32_t)((wn + ((lane >> 4) << 3) + (lane & 7)) * ROWB
                                     + ((lane >> 3) & 1) * 16);

    float acc[2][4][4];     // [m-tile][2*jp+e][frag]
#pragma unroll
    for (int i = 0; i < 2; ++i)
#pragma unroll
        for (int j = 0; j < 4; ++j)
#pragma unroll
            for (int q = 0; q < 4; ++q) acc[i][j][q] = 0.f;

    float4 av[2][2];    // A double-buffered LDG registers (rows +0,+32)

    auto BCP = [&](int t) {     // cp.async B chunk t into stage t%NSTG
        const uint32_t st = sbase + (t % NSTG) * STAGE;
        const unsigned short* bp = bptr + (size_t)t * BKk;
#pragma unroll
        for (int p = 0; p < 2; ++p)
            cpa16(st + OB + b_sts + p * (64 * ROWB), bp + (size_t)p * 64 * NN);
    };
    auto ALDG = [&](int t, int set) {
        const float* ap = aptr + (size_t)t * BKk;
#pragma unroll
        for (int p = 0; p < 2; ++p)
            av[set][p] = *(const float4*)(ap + (size_t)p * 32 * NN);
    };
    auto ASTS = [&](int t, int set) {
        const uint32_t st = sbase + (t % NSTG) * STAGE;
#pragma unroll
        for (int p = 0; p < 2; ++p) {
            uint32_t w0 = pkhf(av[set][p].x * ASCALE, av[set][p].y * ASCALE);
            uint32_t w1 = pkhf(av[set][p].z * ASCALE, av[set][p].w * ASCALE);
            sts64(st + OA + a_sts + p * (32 * ROWB), w0, w1);
        }
    };
    auto COMPUTE = [&](int t) {
        const uint32_t st = sbase + (t % NSTG) * STAGE;
#pragma unroll
        for (int ks = 0; ks < 2; ++ks) {
            uint32_t ah[2][4];
            ldm4(ah[0], st + OA + a_ld + ks * 32);
            ldm4(ah[1], st + OA + a_ld + 16 * ROWB + ks * 32);
#pragma unroll
            for (int jp = 0; jp < 2; ++jp) {
                uint32_t b[4];
                ldm4(b, st + OB + b_ld + jp * (16 * ROWB) + ks * 32);
                mma16816(acc[0][2 * jp],     ah[0], b[0], b[1]);
                mma16816(acc[0][2 * jp + 1], ah[0], b[2], b[3]);
                mma16816(acc[1][2 * jp],     ah[1], b[0], b[1]);
                mma16816(acc[1][2 * jp + 1], ah[1], b[2], b[3]);
            }
        }
    };

    // prologue: B chunks 0,1 committed; A chunks 0,1 in regs; A stage0 stored.
    // cp_wait1 -> chunk 0 complete for THIS thread; sync publishes to all.
    BCP(0); cp_commit();
    BCP(1); cp_commit();
    ALDG(0, 0);
    ALDG(1, 1);
    ASTS(0, 0);
    cp_wait1();
    __syncthreads();

    int cur = 1;
    for (int t = 0; t < NT; ++t) {
        if (t + 2 < NT) BCP(t + 2);
        cp_commit();                            // uniform commit (may be empty)
        if (t + 2 < NT) ALDG(t + 2, cur ^ 1);
        COMPUTE(t);                             // stage t resident (prev wait+sync)
        if (t + 1 < NT) ASTS(t + 1, cur);
        cp_wait1();                             // my chunk t+1 copies complete
        __syncthreads();                        // publish everyone's chunk t+1
        cur ^= 1;
    }

    // epilogue: write raw (scaled) partials
    float* gacc = (kh ? g_acc1 : g_acc0);
    const int r0 = m0 + wm + (lane >> 2);
    const int cb = wn + (lane & 3) * 2;
#pragma unroll
    for (int i = 0; i < 2; ++i) {
#pragma unroll
        for (int j = 0; j < 4; ++j) {
            const int rr = r0 + i * 16;
            const int col = cb + j * 8;
            *(float2*)&gacc[(size_t)rr * HC + col] =
                make_float2(acc[i][j][0], acc[i][j][1]);
            *(float2*)&gacc[(size_t)(rr + 8) * HC + col] =
                make_float2(acc[i][j][2], acc[i][j][3]);
        }
    }
}

// ---------------------------------------------------------------------------
// Kernel 3: h = PReLU((acc0+acc1)/8192 + bias), fused per-slab colsums of
// h1*msk and msk partials. grid 128 blocks (64 rows each) x 256 threads.
// ---------------------------------------------------------------------------
__global__ void __launch_bounds__(256) epi_colsum(
    const float* __restrict__ bias, const float* __restrict__ alphap,
    const float* __restrict__ msk) {
    __shared__ float sp[2][64];
    __shared__ float sm[64];
    const int b = blockIdx.x, tid = threadIdx.x;
    const int c = tid & 127, rg = tid >> 7;
    const int base = b * 64;
    const float alpha = __ldg(alphap);
    const float bi = __ldg(&bias[c & 63]);

    float csum = 0.f;
#pragma unroll 4
    for (int i = 0; i < 32; ++i) {
        const int n = base + rg + 2 * i;
        const size_t idx = (size_t)n * HC + c;
        float v = (g_acc0[idx] + g_acc1[idx]) * ASCALE_I + bi;
        v = v > 0.f ? v : alpha * v;
        g_h[idx] = v;
        csum += msk[n] * v;     // only meaningful for c<64 (h1)
    }
    if (c < 64) sp[rg][c] = csum;
    if (tid < 64) sm[tid] = msk[base + tid];
    __syncthreads();

    if (tid < 64) g_part[b * 64 + tid] = sp[0][tid] + sp[1][tid];
    if (tid < 32) {
        float m = sm[tid] + sm[tid + 32];
#pragma unroll
        for (int o = 16; o; o >>= 1) m += __shfl_down_sync(0xffffffffu, m, o);
        if (tid == 0) g_mskpart[b] = m;
    }
}

// ---------------------------------------------------------------------------
// Kernel 4: c = sigmoid(colsum/msksum); wc = disc_w @ c
// ---------------------------------------------------------------------------
__global__ void __launch_bounds__(256) make_wc2(const float* __restrict__ disc_w) {
    __shared__ float red[4][64];
    __shared__ float cvec[64];
    __shared__ float smm[128];
    __shared__ float msum_s;
    const int tid = threadIdx.x;
    const int g = tid >> 6, col = tid & 63;

    float s = 0.f;
#pragma unroll
    for (int b = 0; b < 32; ++b) s += g_part[(g * 32 + b) * 64 + col];
    red[g][col] = s;

    if (tid < 128) smm[tid] = g_mskpart[tid];
    __syncthreads();
    if (tid < 32) {
        float m = smm[tid] + smm[tid + 32] + smm[tid + 64] + smm[tid + 96];
#pragma unroll
        for (int o = 16; o; o >>= 1) m += __shfl_down_sync(0xffffffffu, m, o);
        if (tid == 0) msum_s = m;
    }
    __syncthreads();
    if (tid < 64) {
        float cv = (red[0][tid] + red[1][tid] + red[2][tid] + red[3][tid]) / msum_s;
        cvec[tid] = 1.f / (1.f + expf(-cv));
    }
    __syncthreads();

    const int j = tid >> 2, q = tid & 3;
    float r = 0.f;
#pragma unroll
    for (int k = 0; k < 16; ++k) r += disc_w[j * 64 + q * 16 + k] * cvec[q * 16 + k];
    r += __shfl_down_sync(0xffffffffu, r, 2);
    r += __shfl_down_sync(0xffffffffu, r, 1);
    if (q == 0) g_wc[j] = r;
}

// ---------------------------------------------------------------------------
// Kernel 5: out[n] = h1[n,:].wc + b ; out[N+n] = h2[n,:].wc + b
// ---------------------------------------------------------------------------
__global__ void __launch_bounds__(256) scores(const float* __restrict__ db,
                                              float* __restrict__ out) {
    const int warp = threadIdx.x >> 5, lane = threadIdx.x & 31;
    const int n = blockIdx.x * 8 + warp;
    const float2* hp = (const float2*)(g_h + (size_t)n * HC);
    const float2 w2 = ((const float2*)g_wc)[lane];
    const float2 v1 = hp[lane];
    const float2 v2 = hp[32 + lane];
    float s1 = v1.x * w2.x + v1.y * w2.y;
    float s2 = v2.x * w2.x + v2.y * w2.y;
#pragma unroll
    for (int o = 16; o; o >>= 1) {
        s1 += __shfl_down_sync(0xffffffffu, s1, o);
        s2 += __shfl_down_sync(0xffffffffu, s2, o);
    }
    if (lane == 0) {
        const float bb = __ldg(db);
        out[n] = s1 + bb;
        out[NN + n] = s2 + bb;
    }
}

// ---------------------------------------------------------------------------
// Inputs: seq1, seq2, adj, msk, fc_w, gcn_bias, prelu_alpha, disc_w, disc_b
// Output: [1, 2N] float32
// ---------------------------------------------------------------------------
extern "C" void kernel_launch(void* const* d_in, const int* in_sizes, int n_in,
                              void* d_out, int out_size) {
    const float* seq1  = (const float*)d_in[0];
    const float* seq2  = (const float*)d_in[1];
    const float* adj   = (const float*)d_in[2];
    const float* msk   = (const float*)d_in[3];
    const float* fcw   = (const float*)d_in[4];
    const float* gbias = (const float*)d_in[5];
    const float* alpha = (const float*)d_in[6];
    const float* discw = (const float*)d_in[7];
    const float* discb = (const float*)d_in[8];
    float* out = (float*)d_out;

    cudaFuncSetAttribute(gemm_mma, cudaFuncAttributeMaxDynamicSharedMemorySize,
                         DYN_SMEM);

    fts_kernel<<<NN / 16, 128>>>(seq1, seq2, fcw);
    gemm_mma<<<(NN / BM) * 2, 256, DYN_SMEM>>>(adj);
    epi_colsum<<<128, 256>>>(gbias, alpha, msk);
    make_wc2<<<1, 256>>>(discw);
    scores<<<NN / 8, 256>>>(discb, out);
}